// round 16
// baseline (speedup 1.0000x reference)
#include <cuda_runtime.h>
#include <cuda_bf16.h>
#include <math.h>
#include <cstdint>

#define NAGT 1024
#define RNN  128
#define NMIX 20

typedef unsigned long long ull;
typedef unsigned int uint;

// ---------------- device scratch ----------------
__device__ float g_xin[NAGT * 128];          // [emb(64) | pool(64)]
__device__ float g_Hs[NAGT * 4096];          // Hs[m][g*64+e], 16 MB
__device__ float g_gatesA[NAGT * 512];       // xin @ W_ih^T
__device__ float g_gatesB[NAGT * 512];       // h0 @ W_hh^T
__device__ float g_WihT[128 * 512];          // WihT[k][c] = W_ih[c][k]
__device__ unsigned short g_list[NAGT * NAGT];  // compacted neighbor lists (2MB)
__device__ int g_cnt[NAGT];

// ================= bf16-split helpers ====================================
__device__ __forceinline__ uint pack_hi2(float x, float y, float& lx, float& ly) {
    __nv_bfloat16 hx = __float2bfloat16(x);
    __nv_bfloat16 hy = __float2bfloat16(y);
    lx = x - __bfloat162float(hx);
    ly = y - __bfloat162float(hy);
    __nv_bfloat162 h; h.x = hx; h.y = hy;
    return *(uint*)&h;
}
__device__ __forceinline__ uint pack2(float x, float y) {
    __nv_bfloat162 h; h.x = __float2bfloat16(x); h.y = __float2bfloat16(y);
    return *(uint*)&h;
}
__device__ __forceinline__ void mma16816(float* d, uint a0, uint a1, uint a2, uint a3,
                                         uint b0, uint b1) {
    asm volatile(
        "mma.sync.aligned.m16n8k16.row.col.f32.bf16.bf16.f32 "
        "{%0,%1,%2,%3}, {%4,%5,%6,%7}, {%8,%9}, {%0,%1,%2,%3};"
        : "+f"(d[0]), "+f"(d[1]), "+f"(d[2]), "+f"(d[3])
        : "r"(a0), "r"(a1), "r"(a2), "r"(a3), "r"(b0), "r"(b1));
}

// ---------------- FFMA2 helpers ----------------
__device__ __forceinline__ void ffma2(ull& d, ull a, ull b) {
    asm("fma.rn.f32x2 %0, %1, %2, %0;" : "+l"(d) : "l"(a), "l"(b));
}
__device__ __forceinline__ float2 unpack2(ull v) {
    float2 r;
    asm("mov.b64 {%0,%1}, %2;" : "=f"(r.x), "=f"(r.y) : "l"(v));
    return r;
}
__device__ __forceinline__ ull dup2(float x) {
    ull r;
    asm("mov.b64 %0, {%1,%1};" : "=l"(r) : "f"(x));
    return r;
}

// ---------------- MUFU.TANH-based nonlinearities ----------------
__device__ __forceinline__ float tanh_ap(float x) {
    float y;
    asm("tanh.approx.f32 %0, %1;" : "=f"(y) : "f"(x));
    return y;
}
__device__ __forceinline__ float sigmoid_ap(float x) {
    return fmaf(tanh_ap(0.5f * x), 0.5f, 0.5f);
}

// ================= Kernel A =====================================
// blocks 0..127:   Hs tile 128m x 256n + gatesB slice (tensor)
// blocks 128..135: Wih transpose
// blocks 136..151: neighbor-list building (64 agents each, 1 warp/agent x4)
#define HS_AROW 272
#define HS_A_HI 0
#define HS_A_LO (128 * HS_AROW)
#define HS_B_HI (2 * 128 * HS_AROW)
#define HS_B_LO (HS_B_HI + 256 * HS_AROW)
#define HS_SMEM (HS_B_LO + 256 * HS_AROW)   // 208896

struct GSmem {
    float As[64 * 66];
    float Bs[32 * 130];
};

__global__ void __launch_bounds__(512) kA(const float* __restrict__ h0,
                                          const float* __restrict__ Wsoc,
                                          const float* __restrict__ Whh,
                                          const float* __restrict__ Wih,
                                          const float* __restrict__ xabs) {
    extern __shared__ __align__(16) char sm[];
    const int tid = threadIdx.x;

    if (blockIdx.x >= 136) {
        // ---- neighbor-list build: 64 agents/block, warp handles 4 agents
        float* sx = (float*)sm;              // [1024]
        float* sy = sx + 1024;               // [1024]
        const int b = blockIdx.x - 136;
        const int lane = tid & 31, w = tid >> 5;   // 16 warps
#pragma unroll
        for (int p = 0; p < 2; p++) {
            int i = tid + p * 512;
            float2 pt = *(const float2*)(xabs + 2 * i);
            sx[i] = pt.x; sy[i] = pt.y;
        }
        __syncthreads();
#pragma unroll 1
        for (int s = 0; s < 4; s++) {
            int n = (b * 16 + w) * 4 + s;
            float xn = sx[n] - 0.2f;
            float yn = sy[n] - 0.2f;
            unsigned cnt = 0;
#pragma unroll 4
            for (int t = 0; t < 32; t++) {
                int m = t * 32 + lane;
                float dx = sx[m] - xn;
                float dy = sy[m] - yn;
                bool v = (m != n) && dx >= 0.0f && dx < 0.4f && dy >= 0.0f && dy < 0.4f;
                int cell = 0;
                if (v) {
                    int cx = (int)floorf(dx * 20.0f);
                    int cy = (int)floorf(dy * 20.0f);
                    v = (cx >= 0) && (cx < 8) && (cy >= 0) && (cy < 8);
                    cell = cx + cy * 8;
                }
                unsigned mask = __ballot_sync(0xffffffffu, v);
                if (v) {
                    int pos = cnt + __popc(mask & ((1u << lane) - 1u));
                    g_list[n * NAGT + pos] = (unsigned short)((m << 6) | cell);
                }
                cnt += __popc(mask);
            }
            if (lane == 0) g_cnt[n] = (int)cnt;
        }
        return;
    }
    if (blockIdx.x >= 128) {
        // ---- Wih transpose: block t -> WihT cols [64t, 64t+64) ----
        float* tile = (float*)sm;            // [64][130]
        const int t = blockIdx.x - 128;
#pragma unroll
        for (int p = 0; p < 4; p++) {
            int idx = tid + p * 512;
            int r = idx >> 5, c4 = idx & 31;
            float4 v = *(const float4*)(Wih + (t * 64 + r) * 128 + c4 * 4);
            tile[r * 130 + c4 * 4 + 0] = v.x;
            tile[r * 130 + c4 * 4 + 1] = v.y;
            tile[r * 130 + c4 * 4 + 2] = v.z;
            tile[r * 130 + c4 * 4 + 3] = v.w;
        }
        __syncthreads();
#pragma unroll
        for (int p = 0; p < 16; p++) {
            int idx = tid + p * 512;
            int k = idx >> 6, j = idx & 63;
            g_WihT[k * 512 + t * 64 + j] = tile[j * 130 + k];
        }
        return;
    }

    const int wid = tid >> 5, lane = tid & 31;
    const int m0 = (blockIdx.x & 7) * 128;
    const int c0 = (blockIdx.x >> 3) * 256;

#pragma unroll
    for (int p = 0; p < 8; p++) {
        int idx = tid + p * 512;
        int r = idx >> 5, c4 = idx & 31;
        float4 v = *(const float4*)(h0 + (m0 + r) * 128 + c4 * 4);
        float lx, ly, lz, lw;
        uint2 H, L;
        H.x = pack_hi2(v.x, v.y, lx, ly);
        H.y = pack_hi2(v.z, v.w, lz, lw);
        L.x = pack2(lx, ly);
        L.y = pack2(lz, lw);
        int off = r * HS_AROW + c4 * 8;
        *(uint2*)(sm + HS_A_HI + off) = H;
        *(uint2*)(sm + HS_A_LO + off) = L;
    }
#pragma unroll
    for (int p = 0; p < 16; p++) {
        int idx = tid + p * 512;
        int r = idx >> 5, c4 = idx & 31;
        int gc = c0 + r;
        float4 v = *(const float4*)(Wsoc + (gc & 63) * 8192 + (gc >> 6) * 128 + c4 * 4);
        float lx, ly, lz, lw;
        uint2 H, L;
        H.x = pack_hi2(v.x, v.y, lx, ly);
        H.y = pack_hi2(v.z, v.w, lz, lw);
        L.x = pack2(lx, ly);
        L.y = pack2(lz, lw);
        int off = r * HS_AROW + c4 * 8;
        *(uint2*)(sm + HS_B_HI + off) = H;
        *(uint2*)(sm + HS_B_LO + off) = L;
    }
    __syncthreads();

    const int wm = (wid >> 2) * 32;
    const int wn = (wid & 3) * 64;
    const int tq = lane >> 2;
    const int tr = lane & 3;

    {
        float acc[2][8][4];
#pragma unroll
        for (int i = 0; i < 2; i++)
#pragma unroll
            for (int j = 0; j < 8; j++)
#pragma unroll
                for (int q = 0; q < 4; q++) acc[i][j][q] = 0.0f;

#pragma unroll 1
        for (int ks = 0; ks < 8; ks++) {
            const int kb = ks * 32 + tr * 4;
            uint aH[2][4], aL[2][4];
#pragma unroll
            for (int mf = 0; mf < 2; mf++) {
                int row = wm + mf * 16 + tq;
                int o0 = row * HS_AROW + kb;
                int o1 = o0 + 8 * HS_AROW;
                aH[mf][0] = *(const uint*)(sm + HS_A_HI + o0);
                aH[mf][1] = *(const uint*)(sm + HS_A_HI + o1);
                aH[mf][2] = *(const uint*)(sm + HS_A_HI + o0 + 16);
                aH[mf][3] = *(const uint*)(sm + HS_A_HI + o1 + 16);
                aL[mf][0] = *(const uint*)(sm + HS_A_LO + o0);
                aL[mf][1] = *(const uint*)(sm + HS_A_LO + o1);
                aL[mf][2] = *(const uint*)(sm + HS_A_LO + o0 + 16);
                aL[mf][3] = *(const uint*)(sm + HS_A_LO + o1 + 16);
            }
#pragma unroll
            for (int nf = 0; nf < 8; nf++) {
                int col = wn + nf * 8 + tq;
                int o0 = col * HS_AROW + kb;
                uint bH0 = *(const uint*)(sm + HS_B_HI + o0);
                uint bH1 = *(const uint*)(sm + HS_B_HI + o0 + 16);
                uint bL0 = *(const uint*)(sm + HS_B_LO + o0);
                uint bL1 = *(const uint*)(sm + HS_B_LO + o0 + 16);
#pragma unroll
                for (int mf = 0; mf < 2; mf++) {
                    mma16816(acc[mf][nf], aH[mf][0], aH[mf][1], aH[mf][2], aH[mf][3], bH0, bH1);
                    mma16816(acc[mf][nf], aH[mf][0], aH[mf][1], aH[mf][2], aH[mf][3], bL0, bL1);
                    mma16816(acc[mf][nf], aL[mf][0], aL[mf][1], aL[mf][2], aL[mf][3], bH0, bH1);
                }
            }
        }
#pragma unroll
        for (int mf = 0; mf < 2; mf++) {
            int row0 = m0 + wm + mf * 16 + tq;
#pragma unroll
            for (int nf = 0; nf < 8; nf++) {
                int col = c0 + wn + nf * 8 + tr * 2;
                *(float2*)&g_Hs[row0 * 4096 + col] =
                    make_float2(acc[mf][nf][0], acc[mf][nf][1]);
                *(float2*)&g_Hs[(row0 + 8) * 4096 + col] =
                    make_float2(acc[mf][nf][2], acc[mf][nf][3]);
            }
        }
    }

    // ---- phase 2: gatesB slice 128m x 32n ----
    __syncthreads();
    const int j0 = (blockIdx.x >> 3) * 32;
#pragma unroll
    for (int p = 0; p < 2; p++) {
        int idx = tid + p * 512;
        int r = idx >> 5, c4 = idx & 31;
        float4 v = *(const float4*)(Whh + (j0 + r) * 128 + c4 * 4);
        float lx, ly, lz, lw;
        uint2 H, L;
        H.x = pack_hi2(v.x, v.y, lx, ly);
        H.y = pack_hi2(v.z, v.w, lz, lw);
        L.x = pack2(lx, ly);
        L.y = pack2(lz, lw);
        int off = r * HS_AROW + c4 * 8;
        *(uint2*)(sm + HS_B_HI + off) = H;
        *(uint2*)(sm + HS_B_LO + off) = L;
    }
    __syncthreads();

    const int wn2 = (wid & 3) * 8;
    float acc2[2][4];
#pragma unroll
    for (int i = 0; i < 2; i++)
#pragma unroll
        for (int q = 0; q < 4; q++) acc2[i][q] = 0.0f;

#pragma unroll 1
    for (int ks = 0; ks < 8; ks++) {
        const int kb = ks * 32 + tr * 4;
        uint aH[2][4], aL[2][4];
#pragma unroll
        for (int mf = 0; mf < 2; mf++) {
            int row = wm + mf * 16 + tq;
            int o0 = row * HS_AROW + kb;
            int o1 = o0 + 8 * HS_AROW;
            aH[mf][0] = *(const uint*)(sm + HS_A_HI + o0);
            aH[mf][1] = *(const uint*)(sm + HS_A_HI + o1);
            aH[mf][2] = *(const uint*)(sm + HS_A_HI + o0 + 16);
            aH[mf][3] = *(const uint*)(sm + HS_A_HI + o1 + 16);
            aL[mf][0] = *(const uint*)(sm + HS_A_LO + o0);
            aL[mf][1] = *(const uint*)(sm + HS_A_LO + o1);
            aL[mf][2] = *(const uint*)(sm + HS_A_LO + o0 + 16);
            aL[mf][3] = *(const uint*)(sm + HS_A_LO + o1 + 16);
        }
        int col = wn2 + tq;
        int o0 = col * HS_AROW + kb;
        uint bH0 = *(const uint*)(sm + HS_B_HI + o0);
        uint bH1 = *(const uint*)(sm + HS_B_HI + o0 + 16);
        uint bL0 = *(const uint*)(sm + HS_B_LO + o0);
        uint bL1 = *(const uint*)(sm + HS_B_LO + o0 + 16);
#pragma unroll
        for (int mf = 0; mf < 2; mf++) {
            mma16816(acc2[mf], aH[mf][0], aH[mf][1], aH[mf][2], aH[mf][3], bH0, bH1);
            mma16816(acc2[mf], aH[mf][0], aH[mf][1], aH[mf][2], aH[mf][3], bL0, bL1);
            mma16816(acc2[mf], aL[mf][0], aL[mf][1], aL[mf][2], aL[mf][3], bH0, bH1);
        }
    }
#pragma unroll
    for (int mf = 0; mf < 2; mf++) {
        int row0 = m0 + wm + mf * 16 + tq;
        int col = j0 + wn2 + tr * 2;
        *(float2*)&g_gatesB[row0 * 512 + col] = make_float2(acc2[mf][0], acc2[mf][1]);
        *(float2*)&g_gatesB[(row0 + 8) * 512 + col] = make_float2(acc2[mf][2], acc2[mf][3]);
    }
}

// ---------------- k_pool: gather-only (+ fused emb), grid=1024 x 128 -----
__global__ void __launch_bounds__(128) k_pool(const float* __restrict__ b_soc,
                                              const float* __restrict__ xoff,
                                              const float* __restrict__ W_emb,
                                              const float* __restrict__ b_emb) {
    __shared__ float red[4][64];
    const int n = blockIdx.x;
    const int tid = threadIdx.x;
    const int lane = tid & 31, w = tid >> 5;   // 4 warps

    if (tid < 64) {
        float v = b_emb[tid];
        v = fmaf(xoff[2 * n + 0], W_emb[2 * tid + 0], v);
        v = fmaf(xoff[2 * n + 1], W_emb[2 * tid + 1], v);
        g_xin[n * 128 + tid] = fmaxf(v, 0.0f);
    }

    const int cnt = g_cnt[n];
    const unsigned short* lst = g_list + n * NAGT;

    // warp w takes entries w, w+4, w+8, ... ; unroll 4 (stride 16)
    float2 ac0 = make_float2(0.f, 0.f), ac1 = make_float2(0.f, 0.f);
    float2 ac2 = make_float2(0.f, 0.f), ac3 = make_float2(0.f, 0.f);
    int i = w;
    for (; i + 12 < cnt; i += 16) {
        unsigned v0 = lst[i];
        unsigned v1 = lst[i + 4];
        unsigned v2 = lst[i + 8];
        unsigned v3 = lst[i + 12];
        float2 t0 = *(const float2*)(g_Hs + (v0 >> 6) * 4096 + (v0 & 63) * 64 + lane * 2);
        float2 t1 = *(const float2*)(g_Hs + (v1 >> 6) * 4096 + (v1 & 63) * 64 + lane * 2);
        float2 t2 = *(const float2*)(g_Hs + (v2 >> 6) * 4096 + (v2 & 63) * 64 + lane * 2);
        float2 t3 = *(const float2*)(g_Hs + (v3 >> 6) * 4096 + (v3 & 63) * 64 + lane * 2);
        ac0.x += t0.x; ac0.y += t0.y;
        ac1.x += t1.x; ac1.y += t1.y;
        ac2.x += t2.x; ac2.y += t2.y;
        ac3.x += t3.x; ac3.y += t3.y;
    }
    for (; i < cnt; i += 4) {
        unsigned v0 = lst[i];
        float2 t0 = *(const float2*)(g_Hs + (v0 >> 6) * 4096 + (v0 & 63) * 64 + lane * 2);
        ac0.x += t0.x; ac0.y += t0.y;
    }
    *(float2*)&red[w][lane * 2] =
        make_float2(ac0.x + ac1.x + ac2.x + ac3.x, ac0.y + ac1.y + ac2.y + ac3.y);
    __syncthreads();

    if (tid < 64) {
        float sum = red[0][tid] + red[1][tid] + red[2][tid] + red[3][tid] + b_soc[tid];
        g_xin[n * 128 + 64 + tid] = fmaxf(sum, 0.0f);
    }
}

// ---------------- gatesA: xin @ Wih^T, grid=(16,4), 256 thr --------------
__global__ void __launch_bounds__(256) k_gatesA(const float* __restrict__ Wih) {
    __shared__ __align__(16) GSmem s;
    const int m0 = blockIdx.x * 64;
    const int j0 = blockIdx.y * 128;
    const int tid = threadIdx.x;
    const int tx = tid & 15, ty = tid >> 4;

    const float* Bw = Wih + j0 * 128;

    ull acc[4][4];
#pragma unroll
    for (int i = 0; i < 4; i++)
#pragma unroll
        for (int j = 0; j < 4; j++) acc[i][j] = 0ull;

#pragma unroll 1
    for (int kc = 0; kc < 4; kc++) {
        const int kb = kc * 32;
#pragma unroll
        for (int p = 0; p < 2; p++) {
            int idx = tid + p * 256;
            int k4 = idx & 7, m = idx >> 3;
            float4 v = *(const float4*)(g_xin + (m0 + m) * 128 + kb + k4 * 4);
            int base = m * 66 + k4 * 8;
            *(ull*)&s.As[base + 0] = dup2(v.x);
            *(ull*)&s.As[base + 2] = dup2(v.y);
            *(ull*)&s.As[base + 4] = dup2(v.z);
            *(ull*)&s.As[base + 6] = dup2(v.w);
        }
#pragma unroll
        for (int p = 0; p < 4; p++) {
            int idx = tid + p * 256;
            int k4 = idx & 7, c = idx >> 3;
            float4 v = *(const float4*)(Bw + c * 128 + kb + k4 * 4);
            s.Bs[(k4 * 4 + 0) * 130 + c] = v.x;
            s.Bs[(k4 * 4 + 1) * 130 + c] = v.y;
            s.Bs[(k4 * 4 + 2) * 130 + c] = v.z;
            s.Bs[(k4 * 4 + 3) * 130 + c] = v.w;
        }
        __syncthreads();
#pragma unroll 4
        for (int k = 0; k < 32; k++) {
            ull bb[4];
#pragma unroll
            for (int j = 0; j < 4; j++)
                bb[j] = *(const ull*)&s.Bs[k * 130 + 2 * tx + 32 * j];
#pragma unroll
            for (int i = 0; i < 4; i++) {
                ull a = *(const ull*)&s.As[(ty * 4 + i) * 66 + 2 * k];
#pragma unroll
                for (int j = 0; j < 4; j++) ffma2(acc[i][j], a, bb[j]);
            }
        }
        __syncthreads();
    }
#pragma unroll
    for (int i = 0; i < 4; i++) {
        int m = m0 + ty * 4 + i;
#pragma unroll
        for (int j = 0; j < 4; j++) {
            float2 v = unpack2(acc[i][j]);
            *(float2*)&g_gatesA[m * 512 + j0 + 2 * tx + 32 * j] = v;
        }
    }
}

// ---------------- Kernel D: fused LSTM elementwise + out GEMM (r12) ------
#define KD_WOT_PAD 121
#define KD_SMEM ((8 * 128 + 128 * KD_WOT_PAD) * 4)   // 66048 B

__global__ void __launch_bounds__(512) kD(const float* __restrict__ c0v,
                                          const float* __restrict__ b_ih,
                                          const float* __restrict__ b_hh,
                                          const float* __restrict__ Wout,
                                          const float* __restrict__ b_out,
                                          float* __restrict__ out) {
    extern __shared__ float sdynf[];
    float* Hn  = sdynf;                 // [8][128]
    float* WoT = sdynf + 8 * 128;       // [128][121]
    const int m0 = blockIdx.x * 8;
    const int tid = threadIdx.x;

#pragma unroll
    for (int p = 0; p < 2; p++) {
        int id = tid + p * 512;
        int r = id >> 7, k = id & 127;
        const float* ga = g_gatesA + (m0 + r) * 512;
        const float* gb = g_gatesB + (m0 + r) * 512;
        float iv = ga[k]       + gb[k]       + b_ih[k]       + b_hh[k];
        float fv = ga[128 + k] + gb[128 + k] + b_ih[128 + k] + b_hh[128 + k];
        float gv = ga[256 + k] + gb[256 + k] + b_ih[256 + k] + b_hh[256 + k];
        float ov = ga[384 + k] + gb[384 + k] + b_ih[384 + k] + b_hh[384 + k];
        float si = sigmoid_ap(iv);
        float sf = sigmoid_ap(fv);
        float so = sigmoid_ap(ov);
        float c  = sf * c0v[(m0 + r) * 128 + k] + si * tanh_ap(gv);
        Hn[r * 128 + k] = so * tanh_ap(c);
    }

    for (int i = tid; i < 120 * 32; i += 512) {
        int c = i >> 5, k4 = i & 31;
        float4 v = *(const float4*)(Wout + c * 128 + k4 * 4);
        WoT[(k4 * 4 + 0) * KD_WOT_PAD + c] = v.x;
        WoT[(k4 * 4 + 1) * KD_WOT_PAD + c] = v.y;
        WoT[(k4 * 4 + 2) * KD_WOT_PAD + c] = v.z;
        WoT[(k4 * 4 + 3) * KD_WOT_PAD + c] = v.w;
    }
    __syncthreads();

    const int ty = tid >> 7;            // 0..3 -> rows ty*2, ty*2+1
    const int tx = tid & 127;           // col (active < 120)
    if (tx < 120) {
        const float* h0r = Hn + (ty * 2 + 0) * 128;
        const float* h1r = Hn + (ty * 2 + 1) * 128;
        float acc0 = 0.0f, acc1 = 0.0f;
#pragma unroll 8
        for (int k = 0; k < 128; k++) {
            float b = WoT[k * KD_WOT_PAD + tx];
            acc0 = fmaf(h0r[k], b, acc0);
            acc1 = fmaf(h1r[k], b, acc1);
        }
        float bo = b_out[tx];
        int cdiv = tx / 20, cmod = tx % 20;
        int n0 = m0 + ty * 2;
        out[cdiv * (NAGT * NMIX) + n0 * NMIX + cmod]       = acc0 + bo;
        out[cdiv * (NAGT * NMIX) + (n0 + 1) * NMIX + cmod] = acc1 + bo;
    }
}

// ---------------- launch ----------------
extern "C" void kernel_launch(void* const* d_in, const int* in_sizes, int n_in,
                              void* d_out, int out_size) {
    const float* xoff  = (const float*)d_in[0];
    const float* xabs  = (const float*)d_in[1];
    const float* h0    = (const float*)d_in[2];
    const float* c0    = (const float*)d_in[3];
    const float* W_emb = (const float*)d_in[4];
    const float* b_emb = (const float*)d_in[5];
    const float* W_soc = (const float*)d_in[6];
    const float* b_soc = (const float*)d_in[7];
    const float* W_ih  = (const float*)d_in[8];
    const float* W_hh  = (const float*)d_in[9];
    const float* b_ih  = (const float*)d_in[10];
    const float* b_hh  = (const float*)d_in[11];
    const float* W_out = (const float*)d_in[12];
    const float* b_out = (const float*)d_in[13];
    float* out = (float*)d_out;

    cudaFuncSetAttribute(kA, cudaFuncAttributeMaxDynamicSharedMemorySize, HS_SMEM);
    cudaFuncSetAttribute(kD, cudaFuncAttributeMaxDynamicSharedMemorySize, KD_SMEM);

    kA<<<152, 512, HS_SMEM>>>(h0, W_soc, W_hh, W_ih, xabs);
    k_pool<<<NAGT, 128>>>(b_soc, xoff, W_emb, b_emb);
    k_gatesA<<<dim3(16, 4), 256>>>(W_ih);
    kD<<<128, 512, KD_SMEM>>>(c0, b_ih, b_hh, W_out, b_out, out);
}

// round 17
// speedup vs baseline: 1.4554x; 1.4554x over previous
#include <cuda_runtime.h>
#include <cuda_bf16.h>
#include <math.h>
#include <cstdint>

#define NAGT 1024
#define RNN  128
#define NMIX 20

typedef unsigned long long ull;
typedef unsigned int uint;

// ---------------- device scratch ----------------
__device__ float g_Hs[NAGT * 4096];          // Hs[m][g*64+e], 16 MB
__device__ float g_gatesA[NAGT * 512];       // xin @ W_ih^T
__device__ float g_gatesB[NAGT * 512];       // h0 @ W_hh^T
__device__ float g_WihT[128 * 512];          // WihT[k][c] = W_ih[c][k]

// ================= bf16-split helpers ====================================
__device__ __forceinline__ uint pack_hi2(float x, float y, float& lx, float& ly) {
    __nv_bfloat16 hx = __float2bfloat16(x);
    __nv_bfloat16 hy = __float2bfloat16(y);
    lx = x - __bfloat162float(hx);
    ly = y - __bfloat162float(hy);
    __nv_bfloat162 h; h.x = hx; h.y = hy;
    return *(uint*)&h;
}
__device__ __forceinline__ uint pack2(float x, float y) {
    __nv_bfloat162 h; h.x = __float2bfloat16(x); h.y = __float2bfloat16(y);
    return *(uint*)&h;
}
__device__ __forceinline__ void mma16816(float* d, uint a0, uint a1, uint a2, uint a3,
                                         uint b0, uint b1) {
    asm volatile(
        "mma.sync.aligned.m16n8k16.row.col.f32.bf16.bf16.f32 "
        "{%0,%1,%2,%3}, {%4,%5,%6,%7}, {%8,%9}, {%0,%1,%2,%3};"
        : "+f"(d[0]), "+f"(d[1]), "+f"(d[2]), "+f"(d[3])
        : "r"(a0), "r"(a1), "r"(a2), "r"(a3), "r"(b0), "r"(b1));
}

// ---------------- MUFU.TANH-based nonlinearities ----------------
__device__ __forceinline__ float tanh_ap(float x) {
    float y;
    asm("tanh.approx.f32 %0, %1;" : "=f"(y) : "f"(x));
    return y;
}
__device__ __forceinline__ float sigmoid_ap(float x) {
    return fmaf(tanh_ap(0.5f * x), 0.5f, 0.5f);
}

// ================= Kernel A (exact r12) ==================================
// blocks 0..127: Hs tile 128m x 256n + gatesB slice 128m x 32n (tensor)
// blocks 128..135: Wih transpose (64 cols of WihT each)
#define HS_AROW 272
#define HS_A_HI 0
#define HS_A_LO (128 * HS_AROW)
#define HS_B_HI (2 * 128 * HS_AROW)
#define HS_B_LO (HS_B_HI + 256 * HS_AROW)
#define HS_SMEM (HS_B_LO + 256 * HS_AROW)   // 208896

__global__ void __launch_bounds__(512) kA(const float* __restrict__ h0,
                                          const float* __restrict__ Wsoc,
                                          const float* __restrict__ Whh,
                                          const float* __restrict__ Wih) {
    extern __shared__ __align__(16) char sm[];
    const int tid = threadIdx.x;

    if (blockIdx.x >= 128) {
        // ---- Wih transpose: block t -> WihT cols [64t, 64t+64) ----
        float* tile = (float*)sm;            // [64][130]
        const int t = blockIdx.x - 128;
#pragma unroll
        for (int p = 0; p < 4; p++) {
            int idx = tid + p * 512;         // 2048 float4 = 64 rows x 32 c4
            int r = idx >> 5, c4 = idx & 31;
            float4 v = *(const float4*)(Wih + (t * 64 + r) * 128 + c4 * 4);
            tile[r * 130 + c4 * 4 + 0] = v.x;
            tile[r * 130 + c4 * 4 + 1] = v.y;
            tile[r * 130 + c4 * 4 + 2] = v.z;
            tile[r * 130 + c4 * 4 + 3] = v.w;
        }
        __syncthreads();
#pragma unroll
        for (int p = 0; p < 16; p++) {
            int idx = tid + p * 512;         // 8192 = 128 k x 64 j
            int k = idx >> 6, j = idx & 63;
            g_WihT[k * 512 + t * 64 + j] = tile[j * 130 + k];
        }
        return;
    }

    const int wid = tid >> 5, lane = tid & 31;
    const int m0 = (blockIdx.x & 7) * 128;
    const int c0 = (blockIdx.x >> 3) * 256;

    // ---- fill A: h0 tile 128 x 128 -> bf16 hi/lo ----
#pragma unroll
    for (int p = 0; p < 8; p++) {
        int idx = tid + p * 512;
        int r = idx >> 5, c4 = idx & 31;
        float4 v = *(const float4*)(h0 + (m0 + r) * 128 + c4 * 4);
        float lx, ly, lz, lw;
        uint2 H, L;
        H.x = pack_hi2(v.x, v.y, lx, ly);
        H.y = pack_hi2(v.z, v.w, lz, lw);
        L.x = pack2(lx, ly);
        L.y = pack2(lz, lw);
        int off = r * HS_AROW + c4 * 8;
        *(uint2*)(sm + HS_A_HI + off) = H;
        *(uint2*)(sm + HS_A_LO + off) = L;
    }
    // ---- fill B: Wsoc-derived 256 x 128 ----
#pragma unroll
    for (int p = 0; p < 16; p++) {
        int idx = tid + p * 512;
        int r = idx >> 5, c4 = idx & 31;
        int gc = c0 + r;
        float4 v = *(const float4*)(Wsoc + (gc & 63) * 8192 + (gc >> 6) * 128 + c4 * 4);
        float lx, ly, lz, lw;
        uint2 H, L;
        H.x = pack_hi2(v.x, v.y, lx, ly);
        H.y = pack_hi2(v.z, v.w, lz, lw);
        L.x = pack2(lx, ly);
        L.y = pack2(lz, lw);
        int off = r * HS_AROW + c4 * 8;
        *(uint2*)(sm + HS_B_HI + off) = H;
        *(uint2*)(sm + HS_B_LO + off) = L;
    }
    __syncthreads();

    const int wm = (wid >> 2) * 32;
    const int wn = (wid & 3) * 64;
    const int tq = lane >> 2;
    const int tr = lane & 3;

    {
        float acc[2][8][4];
#pragma unroll
        for (int i = 0; i < 2; i++)
#pragma unroll
            for (int j = 0; j < 8; j++)
#pragma unroll
                for (int q = 0; q < 4; q++) acc[i][j][q] = 0.0f;

#pragma unroll 1
        for (int ks = 0; ks < 8; ks++) {
            const int kb = ks * 32 + tr * 4;
            uint aH[2][4], aL[2][4];
#pragma unroll
            for (int mf = 0; mf < 2; mf++) {
                int row = wm + mf * 16 + tq;
                int o0 = row * HS_AROW + kb;
                int o1 = o0 + 8 * HS_AROW;
                aH[mf][0] = *(const uint*)(sm + HS_A_HI + o0);
                aH[mf][1] = *(const uint*)(sm + HS_A_HI + o1);
                aH[mf][2] = *(const uint*)(sm + HS_A_HI + o0 + 16);
                aH[mf][3] = *(const uint*)(sm + HS_A_HI + o1 + 16);
                aL[mf][0] = *(const uint*)(sm + HS_A_LO + o0);
                aL[mf][1] = *(const uint*)(sm + HS_A_LO + o1);
                aL[mf][2] = *(const uint*)(sm + HS_A_LO + o0 + 16);
                aL[mf][3] = *(const uint*)(sm + HS_A_LO + o1 + 16);
            }
#pragma unroll
            for (int nf = 0; nf < 8; nf++) {
                int col = wn + nf * 8 + tq;
                int o0 = col * HS_AROW + kb;
                uint bH0 = *(const uint*)(sm + HS_B_HI + o0);
                uint bH1 = *(const uint*)(sm + HS_B_HI + o0 + 16);
                uint bL0 = *(const uint*)(sm + HS_B_LO + o0);
                uint bL1 = *(const uint*)(sm + HS_B_LO + o0 + 16);
#pragma unroll
                for (int mf = 0; mf < 2; mf++) {
                    mma16816(acc[mf][nf], aH[mf][0], aH[mf][1], aH[mf][2], aH[mf][3], bH0, bH1);
                    mma16816(acc[mf][nf], aH[mf][0], aH[mf][1], aH[mf][2], aH[mf][3], bL0, bL1);
                    mma16816(acc[mf][nf], aL[mf][0], aL[mf][1], aL[mf][2], aL[mf][3], bH0, bH1);
                }
            }
        }
#pragma unroll
        for (int mf = 0; mf < 2; mf++) {
            int row0 = m0 + wm + mf * 16 + tq;
#pragma unroll
            for (int nf = 0; nf < 8; nf++) {
                int col = c0 + wn + nf * 8 + tr * 2;
                *(float2*)&g_Hs[row0 * 4096 + col] =
                    make_float2(acc[mf][nf][0], acc[mf][nf][1]);
                *(float2*)&g_Hs[(row0 + 8) * 4096 + col] =
                    make_float2(acc[mf][nf][2], acc[mf][nf][3]);
            }
        }
    }

    // ---- phase 2: gatesB slice 128m x 32n ----
    __syncthreads();
    const int j0 = (blockIdx.x >> 3) * 32;
#pragma unroll
    for (int p = 0; p < 2; p++) {
        int idx = tid + p * 512;
        int r = idx >> 5, c4 = idx & 31;
        float4 v = *(const float4*)(Whh + (j0 + r) * 128 + c4 * 4);
        float lx, ly, lz, lw;
        uint2 H, L;
        H.x = pack_hi2(v.x, v.y, lx, ly);
        H.y = pack_hi2(v.z, v.w, lz, lw);
        L.x = pack2(lx, ly);
        L.y = pack2(lz, lw);
        int off = r * HS_AROW + c4 * 8;
        *(uint2*)(sm + HS_B_HI + off) = H;
        *(uint2*)(sm + HS_B_LO + off) = L;
    }
    __syncthreads();

    const int wn2 = (wid & 3) * 8;
    float acc2[2][4];
#pragma unroll
    for (int i = 0; i < 2; i++)
#pragma unroll
        for (int q = 0; q < 4; q++) acc2[i][q] = 0.0f;

#pragma unroll 1
    for (int ks = 0; ks < 8; ks++) {
        const int kb = ks * 32 + tr * 4;
        uint aH[2][4], aL[2][4];
#pragma unroll
        for (int mf = 0; mf < 2; mf++) {
            int row = wm + mf * 16 + tq;
            int o0 = row * HS_AROW + kb;
            int o1 = o0 + 8 * HS_AROW;
            aH[mf][0] = *(const uint*)(sm + HS_A_HI + o0);
            aH[mf][1] = *(const uint*)(sm + HS_A_HI + o1);
            aH[mf][2] = *(const uint*)(sm + HS_A_HI + o0 + 16);
            aH[mf][3] = *(const uint*)(sm + HS_A_HI + o1 + 16);
            aL[mf][0] = *(const uint*)(sm + HS_A_LO + o0);
            aL[mf][1] = *(const uint*)(sm + HS_A_LO + o1);
            aL[mf][2] = *(const uint*)(sm + HS_A_LO + o0 + 16);
            aL[mf][3] = *(const uint*)(sm + HS_A_LO + o1 + 16);
        }
        int col = wn2 + tq;
        int o0 = col * HS_AROW + kb;
        uint bH0 = *(const uint*)(sm + HS_B_HI + o0);
        uint bH1 = *(const uint*)(sm + HS_B_HI + o0 + 16);
        uint bL0 = *(const uint*)(sm + HS_B_LO + o0);
        uint bL1 = *(const uint*)(sm + HS_B_LO + o0 + 16);
#pragma unroll
        for (int mf = 0; mf < 2; mf++) {
            mma16816(acc2[mf], aH[mf][0], aH[mf][1], aH[mf][2], aH[mf][3], bH0, bH1);
            mma16816(acc2[mf], aH[mf][0], aH[mf][1], aH[mf][2], aH[mf][3], bL0, bL1);
            mma16816(acc2[mf], aL[mf][0], aL[mf][1], aL[mf][2], aL[mf][3], bH0, bH1);
        }
    }
#pragma unroll
    for (int mf = 0; mf < 2; mf++) {
        int row0 = m0 + wm + mf * 16 + tq;
        int col = j0 + wn2 + tr * 2;
        *(float2*)&g_gatesB[row0 * 512 + col] = make_float2(acc2[mf][0], acc2[mf][1]);
        *(float2*)&g_gatesB[(row0 + 8) * 512 + col] = make_float2(acc2[mf][2], acc2[mf][3]);
    }
}

// ---------------- k_pool (r12 scan/gather) + fused gatesA tail -----------
// grid=1024, 256 threads. xin stays in smem; writes g_gatesA directly.
__global__ void __launch_bounds__(256) k_pool(const float* __restrict__ xabs,
                                              const float* __restrict__ b_soc,
                                              const float* __restrict__ xoff,
                                              const float* __restrict__ W_emb,
                                              const float* __restrict__ b_emb) {
    __shared__ float sx[NAGT];
    __shared__ float sy[NAGT];
    __shared__ unsigned short list[NAGT];
    __shared__ unsigned s_cnt[8];
    __shared__ float red[4][64];
    __shared__ float xrow[128];
    const int n = blockIdx.x;
    const int tid = threadIdx.x;

    if (tid < 64) {
        float v = b_emb[tid];
        v = fmaf(xoff[2 * n + 0], W_emb[2 * tid + 0], v);
        v = fmaf(xoff[2 * n + 1], W_emb[2 * tid + 1], v);
        xrow[tid] = fmaxf(v, 0.0f);
    }
    for (int i = tid; i < NAGT; i += 256) {
        float2 p = *(const float2*)(xabs + 2 * i);
        sx[i] = p.x; sy[i] = p.y;
    }
    __syncthreads();

    const float xn = sx[n] - 0.2f;
    const float yn = sy[n] - 0.2f;
    const int lane = tid & 31, w = tid >> 5;

    unsigned cnt = 0;
#pragma unroll
    for (int t = 0; t < 4; t++) {
        int m = w * 128 + t * 32 + lane;
        float dx = sx[m] - xn;
        float dy = sy[m] - yn;
        bool v = (m != n) && dx >= 0.0f && dx < 0.4f && dy >= 0.0f && dy < 0.4f;
        int cell = 0;
        if (v) {
            int cx = (int)floorf(dx * 20.0f);
            int cy = (int)floorf(dy * 20.0f);
            v = (cx >= 0) && (cx < 8) && (cy >= 0) && (cy < 8);
            cell = cx + cy * 8;
        }
        unsigned mask = __ballot_sync(0xffffffffu, v);
        if (v) {
            int pos = cnt + __popc(mask & ((1u << lane) - 1u));
            list[w * 128 + pos] = (unsigned short)((m << 6) | cell);
        }
        cnt += __popc(mask);
    }
    if (lane == 0) s_cnt[w] = cnt;
    __syncthreads();

    const int grp = tid >> 6;
    const int e   = tid & 63;
    float acc = 0.0f;
#pragma unroll
    for (int ws = grp * 2; ws < grp * 2 + 2; ws++) {
        int c = s_cnt[ws];
        for (int i = 0; i < c; i++) {
            unsigned v = list[ws * 128 + i];
            acc += g_Hs[(v >> 6) * 4096 + (v & 63) * 64 + e];
        }
    }
    red[grp][e] = acc;
    __syncthreads();
    if (tid < 64) {
        float sum = red[0][tid] + red[1][tid] + red[2][tid] + red[3][tid] + b_soc[tid];
        xrow[64 + tid] = fmaxf(sum, 0.0f);
    }
    __syncthreads();

    // ---- gatesA tail: thread owns cols {tid, tid+256} ----
    {
        float a0 = 0.0f, a1 = 0.0f;
#pragma unroll 4
        for (int k = 0; k < 128; k++) {
            float xv = xrow[k];
            a0 = fmaf(xv, g_WihT[k * 512 + tid], a0);
            a1 = fmaf(xv, g_WihT[k * 512 + 256 + tid], a1);
        }
        g_gatesA[n * 512 + tid]       = a0;
        g_gatesA[n * 512 + 256 + tid] = a1;
    }
}

// ---------------- Kernel D: fused LSTM elementwise + out GEMM (r12) ------
#define KD_WOT_PAD 121
#define KD_SMEM ((8 * 128 + 128 * KD_WOT_PAD) * 4)   // 66048 B

__global__ void __launch_bounds__(512) kD(const float* __restrict__ c0v,
                                          const float* __restrict__ b_ih,
                                          const float* __restrict__ b_hh,
                                          const float* __restrict__ Wout,
                                          const float* __restrict__ b_out,
                                          float* __restrict__ out) {
    extern __shared__ float sdynf[];
    float* Hn  = sdynf;                 // [8][128]
    float* WoT = sdynf + 8 * 128;       // [128][121]
    const int m0 = blockIdx.x * 8;
    const int tid = threadIdx.x;

#pragma unroll
    for (int p = 0; p < 2; p++) {
        int id = tid + p * 512;
        int r = id >> 7, k = id & 127;
        const float* ga = g_gatesA + (m0 + r) * 512;
        const float* gb = g_gatesB + (m0 + r) * 512;
        float iv = ga[k]       + gb[k]       + b_ih[k]       + b_hh[k];
        float fv = ga[128 + k] + gb[128 + k] + b_ih[128 + k] + b_hh[128 + k];
        float gv = ga[256 + k] + gb[256 + k] + b_ih[256 + k] + b_hh[256 + k];
        float ov = ga[384 + k] + gb[384 + k] + b_ih[384 + k] + b_hh[384 + k];
        float si = sigmoid_ap(iv);
        float sf = sigmoid_ap(fv);
        float so = sigmoid_ap(ov);
        float c  = sf * c0v[(m0 + r) * 128 + k] + si * tanh_ap(gv);
        Hn[r * 128 + k] = so * tanh_ap(c);
    }

    for (int i = tid; i < 120 * 32; i += 512) {
        int c = i >> 5, k4 = i & 31;
        float4 v = *(const float4*)(Wout + c * 128 + k4 * 4);
        WoT[(k4 * 4 + 0) * KD_WOT_PAD + c] = v.x;
        WoT[(k4 * 4 + 1) * KD_WOT_PAD + c] = v.y;
        WoT[(k4 * 4 + 2) * KD_WOT_PAD + c] = v.z;
        WoT[(k4 * 4 + 3) * KD_WOT_PAD + c] = v.w;
    }
    __syncthreads();

    const int ty = tid >> 7;            // 0..3 -> rows ty*2, ty*2+1
    const int tx = tid & 127;           // col (active < 120)
    if (tx < 120) {
        const float* h0r = Hn + (ty * 2 + 0) * 128;
        const float* h1r = Hn + (ty * 2 + 1) * 128;
        float acc0 = 0.0f, acc1 = 0.0f;
#pragma unroll 8
        for (int k = 0; k < 128; k++) {
            float b = WoT[k * KD_WOT_PAD + tx];
            acc0 = fmaf(h0r[k], b, acc0);
            acc1 = fmaf(h1r[k], b, acc1);
        }
        float bo = b_out[tx];
        int cdiv = tx / 20, cmod = tx % 20;
        int n0 = m0 + ty * 2;
        out[cdiv * (NAGT * NMIX) + n0 * NMIX + cmod]       = acc0 + bo;
        out[cdiv * (NAGT * NMIX) + (n0 + 1) * NMIX + cmod] = acc1 + bo;
    }
}

// ---------------- launch ----------------
extern "C" void kernel_launch(void* const* d_in, const int* in_sizes, int n_in,
                              void* d_out, int out_size) {
    const float* xoff  = (const float*)d_in[0];
    const float* xabs  = (const float*)d_in[1];
    const float* h0    = (const float*)d_in[2];
    const float* c0    = (const float*)d_in[3];
    const float* W_emb = (const float*)d_in[4];
    const float* b_emb = (const float*)d_in[5];
    const float* W_soc = (const float*)d_in[6];
    const float* b_soc = (const float*)d_in[7];
    const float* W_ih  = (const float*)d_in[8];
    const float* W_hh  = (const float*)d_in[9];
    const float* b_ih  = (const float*)d_in[10];
    const float* b_hh  = (const float*)d_in[11];
    const float* W_out = (const float*)d_in[12];
    const float* b_out = (const float*)d_in[13];
    float* out = (float*)d_out;

    cudaFuncSetAttribute(kA, cudaFuncAttributeMaxDynamicSharedMemorySize, HS_SMEM);
    cudaFuncSetAttribute(kD, cudaFuncAttributeMaxDynamicSharedMemorySize, KD_SMEM);

    kA<<<136, 512, HS_SMEM>>>(h0, W_soc, W_hh, W_ih);
    k_pool<<<NAGT, 256>>>(xabs, b_soc, xoff, W_emb, b_emb);
    kD<<<128, 512, KD_SMEM>>>(c0, b_ih, b_hh, W_out, b_out, out);
}